// round 9
// baseline (speedup 1.0000x reference)
#include <cuda_runtime.h>
#include <math.h>

#define NN 50000
#define EE 800000
#define DD 128
#define SCB 512
#define NB1 ((NN + SCB - 1) / SCB)   // 98

// ---- scratch (__device__ globals; no allocation allowed) ----
__device__ int   g_deg[NN];
__device__ int   g_partial[NN];
__device__ int   g_bsum[NB1];
__device__ int   g_boff[NB1];
__device__ int   g_off[NN + 1];
__device__ int   g_cursor[NN];
__device__ float g_dis[NN];
__device__ int2  g_edge[EE];         // (src, __float_as_int(ew*dis[src])), grouped by dst

// ---- f32x2 helpers (sm_10x packed dual-FMA) ----
#define PACK2(o, lo, hi) \
    asm("mov.b64 %0, {%1, %2};" : "=l"(o) : "r"(__float_as_uint(lo)), "r"(__float_as_uint(hi)))
#define FMA2(d, a, b) \
    asm("fma.rn.f32x2 %0, %1, %2, %3;" : "=l"(d) : "l"(a), "l"(b), "l"(d))
#define UNPACK2(lo, hi, in) \
    { unsigned int _l, _h; asm("mov.b64 {%0, %1}, %2;" : "=r"(_l), "=r"(_h) : "l"(in)); \
      lo = __uint_as_float(_l); hi = __uint_as_float(_h); }

// ---------------------------------------------------------------------------
__global__ void k_zero_deg() {
    int i = blockIdx.x * blockDim.x + threadIdx.x;
    if (i < NN) g_deg[i] = 0;
}

__global__ void k_degree(const int* __restrict__ ei) {
    int e = blockIdx.x * blockDim.x + threadIdx.x;
    if (e < EE) atomicAdd(&g_deg[ei[EE + e]], 1);
}

// exclusive scan, stage 1: per-block scan + block sums
__global__ void k_scan1() {
    __shared__ int sh[SCB];
    int i = blockIdx.x * SCB + threadIdx.x;
    int v = (i < NN) ? g_deg[i] : 0;
    sh[threadIdx.x] = v;
    __syncthreads();
    for (int off = 1; off < SCB; off <<= 1) {
        int t = (threadIdx.x >= off) ? sh[threadIdx.x - off] : 0;
        __syncthreads();
        sh[threadIdx.x] += t;
        __syncthreads();
    }
    if (i < NN) g_partial[i] = sh[threadIdx.x] - v;   // exclusive
    if (threadIdx.x == SCB - 1) g_bsum[blockIdx.x] = sh[SCB - 1];
}

// stage 2: scan of 98 block sums (single block, 128 threads)
__global__ void k_scan2() {
    __shared__ int sh[128];
    int t = threadIdx.x;
    int v = (t < NB1) ? g_bsum[t] : 0;
    sh[t] = v;
    __syncthreads();
    for (int off = 1; off < 128; off <<= 1) {
        int u = (t >= off) ? sh[t - off] : 0;
        __syncthreads();
        sh[t] += u;
        __syncthreads();
    }
    if (t < NB1) g_boff[t] = sh[t] - v;
}

// stage 3: finalize offsets + cursor init + dis
__global__ void k_scan3() {
    int i = blockIdx.x * blockDim.x + threadIdx.x;
    if (i < NN) {
        int off = g_partial[i] + g_boff[i / SCB];
        g_off[i] = off;
        g_cursor[i] = off;
        g_dis[i] = rsqrtf((float)g_deg[i] + 1.0f);
    }
    if (i == 0) g_off[NN] = EE;
}

// bin edges by dst; fold ew*dis[src] into the stored weight
__global__ void k_bin(const int* __restrict__ ei, const float* __restrict__ ew) {
    int e = blockIdx.x * blockDim.x + threadIdx.x;
    if (e >= EE) return;
    int src = ei[e];
    int dst = ei[EE + e];
    float w = ew[e] * g_dis[src];
    int pos = atomicAdd(&g_cursor[dst], 1);
    g_edge[pos] = make_int2(src, __float_as_int(w));
}

// ---------------------------------------------------------------------------
// Fused: CSR aggregate (registers) -> residual -> GEMM (f32x2) -> GELU -> LN
// 256 threads, 32 rows/block. Warp tr owns rows 4*tr..4*tr+3; lane tc owns
// cols 4*tc..4*tc+3.
__global__ __launch_bounds__(256) void fused_kernel(
    const float* __restrict__ x,
    const float* __restrict__ W,      // (D,D) row-major; out_j = sum_k a_k W[j][k]
    const float* __restrict__ bias,
    const float* __restrict__ gamma,
    const float* __restrict__ beta,
    float* __restrict__ out) {
    __shared__ float A_s[32][132];   // [row][k]; reused as H for LN
    __shared__ float Wt[32][132];    // [k][j]

    const int tid = threadIdx.x;
    const int tr = tid >> 5;
    const int tc = tid & 31;
    const int rowBase = blockIdx.x * 32;

    // ---- Phase A: per-row CSR aggregation into registers ----
#pragma unroll
    for (int i = 0; i < 4; ++i) {
        const int r = 4 * tr + i;
        const int n = rowBase + r;
        float4 a = make_float4(0.f, 0.f, 0.f, 0.f);
        if (n < NN) {
            const int s = g_off[n];
            const int eend = g_off[n + 1];
            int e = s;
            for (; e + 1 < eend; e += 2) {           // 2-edge unroll for MLP
                int2 e0 = g_edge[e];
                int2 e1 = g_edge[e + 1];
                const float4 x0 = *reinterpret_cast<const float4*>(
                    x + (size_t)e0.x * DD + tc * 4);
                const float4 x1 = *reinterpret_cast<const float4*>(
                    x + (size_t)e1.x * DD + tc * 4);
                float w0 = __int_as_float(e0.y);
                float w1 = __int_as_float(e1.y);
                a.x += x0.x * w0; a.y += x0.y * w0; a.z += x0.z * w0; a.w += x0.w * w0;
                a.x += x1.x * w1; a.y += x1.y * w1; a.z += x1.z * w1; a.w += x1.w * w1;
            }
            if (e < eend) {
                int2 e0 = g_edge[e];
                const float4 x0 = *reinterpret_cast<const float4*>(
                    x + (size_t)e0.x * DD + tc * 4);
                float w0 = __int_as_float(e0.y);
                a.x += x0.x * w0; a.y += x0.y * w0; a.z += x0.z * w0; a.w += x0.w * w0;
            }
            const float ds = g_dis[n];
            const float4 xr = *reinterpret_cast<const float4*>(
                x + (size_t)n * DD + tc * 4);
            a.x = a.x * ds + xr.x;
            a.y = a.y * ds + xr.y;
            a.z = a.z * ds + xr.z;
            a.w = a.w * ds + xr.w;
        }
        *reinterpret_cast<float4*>(&A_s[r][4 * tc]) = a;
    }
    __syncthreads();

    // ---- Phase B: GEMM with packed f32x2 FMAs ----
    unsigned long long acc2[4][2];
#pragma unroll
    for (int i = 0; i < 4; ++i) { acc2[i][0] = 0ull; acc2[i][1] = 0ull; }

    for (int kt = 0; kt < 4; ++kt) {
        // stage W tile: Wt[k][j] = W[j][kt*32+k]
#pragma unroll
        for (int t = 0; t < 4; ++t) {
            int idx = tid + t * 256;       // 0..1023 float4s
            int j = idx >> 3;              // 0..127
            int kb = (idx & 7) << 2;       // 0,4,..,28
            float4 w4 = *reinterpret_cast<const float4*>(
                W + (size_t)j * DD + kt * 32 + kb);
            Wt[kb + 0][j] = w4.x;
            Wt[kb + 1][j] = w4.y;
            Wt[kb + 2][j] = w4.z;
            Wt[kb + 3][j] = w4.w;
        }
        __syncthreads();
#pragma unroll
        for (int k = 0; k < 32; ++k) {
            const float4 b = *reinterpret_cast<const float4*>(&Wt[k][4 * tc]);
            unsigned long long b01, b23;
            PACK2(b01, b.x, b.y);
            PACK2(b23, b.z, b.w);
#pragma unroll
            for (int i = 0; i < 4; ++i) {
                const float av = A_s[4 * tr + i][kt * 32 + k];  // smem broadcast
                unsigned long long a2;
                PACK2(a2, av, av);
                FMA2(acc2[i][0], a2, b01);
                FMA2(acc2[i][1], a2, b23);
            }
        }
        __syncthreads();
    }

    // ---- bias + exact GELU; write H into A_s (reuse) ----
    {
        const float4 bv = *reinterpret_cast<const float4*>(bias + 4 * tc);
#pragma unroll
        for (int i = 0; i < 4; ++i) {
            float h0, h1, h2, h3;
            UNPACK2(h0, h1, acc2[i][0]);
            UNPACK2(h2, h3, acc2[i][1]);
            h0 += bv.x; h1 += bv.y; h2 += bv.z; h3 += bv.w;
            float4 hv;
            hv.x = 0.5f * h0 * (1.0f + erff(h0 * 0.70710678118654752f));
            hv.y = 0.5f * h1 * (1.0f + erff(h1 * 0.70710678118654752f));
            hv.z = 0.5f * h2 * (1.0f + erff(h2 * 0.70710678118654752f));
            hv.w = 0.5f * h3 * (1.0f + erff(h3 * 0.70710678118654752f));
            *reinterpret_cast<float4*>(&A_s[4 * tr + i][4 * tc]) = hv;
        }
    }
    __syncthreads();

    // ---- LayerNorm: warp tr handles rows 4*tr..4*tr+3 ----
    const int lane = tc;
#pragma unroll
    for (int s = 0; s < 4; ++s) {
        const int r = 4 * tr + s;
        const int grow = rowBase + r;
        float v0 = A_s[r][lane];
        float v1 = A_s[r][lane + 32];
        float v2 = A_s[r][lane + 64];
        float v3 = A_s[r][lane + 96];
        float sum = v0 + v1 + v2 + v3;
#pragma unroll
        for (int off = 16; off > 0; off >>= 1)
            sum += __shfl_xor_sync(0xFFFFFFFFu, sum, off);
        float mu = sum * (1.0f / DD);
        float d0 = v0 - mu, d1 = v1 - mu, d2 = v2 - mu, d3 = v3 - mu;
        float ss = d0 * d0 + d1 * d1 + d2 * d2 + d3 * d3;
#pragma unroll
        for (int off = 16; off > 0; off >>= 1)
            ss += __shfl_xor_sync(0xFFFFFFFFu, ss, off);
        float inv = rsqrtf(ss * (1.0f / DD) + 1e-5f);
        if (grow < NN) {
            float* op = out + (size_t)grow * DD;
            op[lane]      = d0 * inv * __ldg(gamma + lane)      + __ldg(beta + lane);
            op[lane + 32] = d1 * inv * __ldg(gamma + lane + 32) + __ldg(beta + lane + 32);
            op[lane + 64] = d2 * inv * __ldg(gamma + lane + 64) + __ldg(beta + lane + 64);
            op[lane + 96] = d3 * inv * __ldg(gamma + lane + 96) + __ldg(beta + lane + 96);
        }
    }
}

// ---------------------------------------------------------------------------
extern "C" void kernel_launch(void* const* d_in, const int* in_sizes, int n_in,
                              void* d_out, int out_size) {
    const float* x  = (const float*)d_in[0];   // (N, D) f32
    const int*   ei = (const int*)d_in[1];     // (2, E) int32
    const float* ew = (const float*)d_in[2];   // (E,)  f32
    const float* W  = (const float*)d_in[3];   // (D, D) f32
    const float* b  = (const float*)d_in[4];   // (D,)  f32
    const float* gm = (const float*)d_in[5];   // (D,)  f32
    const float* bt = (const float*)d_in[6];   // (D,)  f32
    float*       out = (float*)d_out;          // (N, D) f32

    (void)in_sizes; (void)n_in; (void)out_size;

    k_zero_deg<<<(NN + 255) / 256, 256>>>();
    k_degree<<<(EE + 255) / 256, 256>>>(ei);
    k_scan1<<<NB1, SCB>>>();
    k_scan2<<<1, 128>>>();
    k_scan3<<<(NN + 255) / 256, 256>>>();
    k_bin<<<(EE + 255) / 256, 256>>>(ei, ew);
    fused_kernel<<<(NN + 31) / 32, 256>>>(x, W, b, gm, bt, out);
}